// round 1
// baseline (speedup 1.0000x reference)
#include <cuda_runtime.h>
#include <math.h>

// ScaledDotProductAttention: B=4, H=16, S=2048, D=64, fp32.
// Flash-attention style: one thread per query row, K/V tiles staged in smem,
// online softmax in chunks of 16 keys (keeps score regs constant-indexed).

#define BATCH 4
#define HEADS 16
#define SEQ   2048
#define HDIM  64

#define TILE_Q 128   // queries per CTA (= threads per CTA)
#define TILE_K 64    // keys per smem tile
#define CHUNK  16    // keys per online-softmax chunk

__global__ __launch_bounds__(TILE_Q, 2)
void sdpa_flash_kernel(const float* __restrict__ Q,
                       const float* __restrict__ K,
                       const float* __restrict__ V,
                       float* __restrict__ O) {
    __shared__ float sK[TILE_K * HDIM];
    __shared__ float sV[TILE_K * HDIM];

    const int bh   = blockIdx.y;                       // 0..63 (b*H + h)
    const int qrow = blockIdx.x * TILE_Q + threadIdx.x; // query index in [0,SEQ)

    const float scale = 0.125f; // 1/sqrt(64)

    // Load this thread's query row into registers, pre-scaled.
    const float* Qr = Q + ((size_t)bh * SEQ + qrow) * HDIM;
    float q[HDIM];
#pragma unroll
    for (int d = 0; d < HDIM; d += 4) {
        float4 t = *reinterpret_cast<const float4*>(Qr + d);
        q[d + 0] = t.x * scale;
        q[d + 1] = t.y * scale;
        q[d + 2] = t.z * scale;
        q[d + 3] = t.w * scale;
    }

    float o[HDIM];
#pragma unroll
    for (int d = 0; d < HDIM; d++) o[d] = 0.0f;
    float m = -INFINITY;
    float l = 0.0f;

    const float* Kb = K + (size_t)bh * SEQ * HDIM;
    const float* Vb = V + (size_t)bh * SEQ * HDIM;

    for (int kt = 0; kt < SEQ; kt += TILE_K) {
        __syncthreads();
        // Cooperative tile load: TILE_K*HDIM floats each for K and V.
        {
            const float4* Ksrc = reinterpret_cast<const float4*>(Kb + (size_t)kt * HDIM);
            const float4* Vsrc = reinterpret_cast<const float4*>(Vb + (size_t)kt * HDIM);
            float4* dK = reinterpret_cast<float4*>(sK);
            float4* dV = reinterpret_cast<float4*>(sV);
#pragma unroll
            for (int i = 0; i < (TILE_K * HDIM / 4) / TILE_Q; i++) {
                int idx = i * TILE_Q + threadIdx.x;
                dK[idx] = Ksrc[idx];
                dV[idx] = Vsrc[idx];
            }
        }
        __syncthreads();

        // Process the tile in chunks of CHUNK keys with an online softmax update.
#pragma unroll 1
        for (int c = 0; c < TILE_K; c += CHUNK) {
            float s[CHUNK];
#pragma unroll
            for (int jj = 0; jj < CHUNK; jj++) {
                const float4* kr = reinterpret_cast<const float4*>(sK + (c + jj) * HDIM);
                float acc = 0.0f;
#pragma unroll
                for (int d4 = 0; d4 < HDIM / 4; d4++) {
                    float4 kv = kr[d4];  // broadcast LDS.128 (same addr across warp)
                    acc = fmaf(q[4 * d4 + 0], kv.x, acc);
                    acc = fmaf(q[4 * d4 + 1], kv.y, acc);
                    acc = fmaf(q[4 * d4 + 2], kv.z, acc);
                    acc = fmaf(q[4 * d4 + 3], kv.w, acc);
                }
                s[jj] = acc;
            }

            float cmax = s[0];
#pragma unroll
            for (int jj = 1; jj < CHUNK; jj++) cmax = fmaxf(cmax, s[jj]);

            float mnew = fmaxf(m, cmax);
            float corr = __expf(m - mnew);
            l *= corr;
#pragma unroll
            for (int d = 0; d < HDIM; d++) o[d] *= corr;

#pragma unroll
            for (int jj = 0; jj < CHUNK; jj++) {
                float p = __expf(s[jj] - mnew);
                l += p;
                const float4* vr = reinterpret_cast<const float4*>(sV + (c + jj) * HDIM);
#pragma unroll
                for (int d4 = 0; d4 < HDIM / 4; d4++) {
                    float4 vv = vr[d4];  // broadcast LDS.128
                    o[4 * d4 + 0] = fmaf(p, vv.x, o[4 * d4 + 0]);
                    o[4 * d4 + 1] = fmaf(p, vv.y, o[4 * d4 + 1]);
                    o[4 * d4 + 2] = fmaf(p, vv.z, o[4 * d4 + 2]);
                    o[4 * d4 + 3] = fmaf(p, vv.w, o[4 * d4 + 3]);
                }
            }
            m = mnew;
        }
    }

    const float inv = 1.0f / l;
    float* Or = O + ((size_t)bh * SEQ + qrow) * HDIM;
#pragma unroll
    for (int d = 0; d < HDIM; d += 4) {
        float4 t;
        t.x = o[d + 0] * inv;
        t.y = o[d + 1] * inv;
        t.z = o[d + 2] * inv;
        t.w = o[d + 3] * inv;
        *reinterpret_cast<float4*>(Or + d) = t;
    }
}

extern "C" void kernel_launch(void* const* d_in, const int* in_sizes, int n_in,
                              void* d_out, int out_size) {
    const float* Q = (const float*)d_in[0];
    const float* K = (const float*)d_in[1];
    const float* V = (const float*)d_in[2];
    float* O = (float*)d_out;

    dim3 grid(SEQ / TILE_Q, BATCH * HEADS);
    dim3 block(TILE_Q);
    sdpa_flash_kernel<<<grid, block>>>(Q, K, V, O);
}

// round 8
// speedup vs baseline: 1.5222x; 1.5222x over previous
#include <cuda_runtime.h>
#include <math.h>

// SDPA B=4,H=16,S=2048,D=64 fp32.
// Flash attention, CTA tile 64 queries x 64 keys, 128 threads.
// Thread computes 8 queries x 4 keys (scores) and 8 queries x 4 d-cols (output),
// with f32x2 packed FMA (queries packed in pairs).

#define BATCH 4
#define HEADS 16
#define SEQ   2048
#define HDIM  64
#define TQ    64
#define TK    64
#define NTHREADS 128

#define QS_STRIDE 68
#define KS_STRIDE 68
#define VS_STRIDE 64
#define PS_STRIDE 66

#define QS_OFF 0
#define KS_OFF (64 * QS_STRIDE)
#define VS_OFF (KS_OFF + 64 * KS_STRIDE)
#define PS_OFF (VS_OFF + 64 * VS_STRIDE)
#define SMEM_FLOATS (PS_OFF + 64 * PS_STRIDE)
#define SMEM_BYTES (SMEM_FLOATS * 4)

typedef unsigned long long ull;

__device__ __forceinline__ ull pack2(float lo, float hi) {
    ull r;
    asm("mov.b64 %0, {%1,%2};" : "=l"(r) : "f"(lo), "f"(hi));
    return r;
}
__device__ __forceinline__ void unpack2(ull v, float& lo, float& hi) {
    asm("mov.b64 {%0,%1}, %2;" : "=f"(lo), "=f"(hi) : "l"(v));
}
__device__ __forceinline__ void fma2(ull& d, ull a, ull b) {
    asm("fma.rn.f32x2 %0, %1, %2, %0;" : "+l"(d) : "l"(a), "l"(b));
}
__device__ __forceinline__ void mul2(ull& d, ull a) {
    asm("mul.rn.f32x2 %0, %0, %1;" : "+l"(d) : "l"(a));
}
__device__ __forceinline__ float ex2(float x) {
    float y;
    asm("ex2.approx.ftz.f32 %0, %1;" : "=f"(y) : "f"(x));
    return y;
}

extern __shared__ float smem[];

__global__ __launch_bounds__(NTHREADS, 3)
void sdpa_rt_kernel(const float* __restrict__ Q,
                    const float* __restrict__ K,
                    const float* __restrict__ V,
                    float* __restrict__ O) {
    float* Qs = smem + QS_OFF;
    float* Ks = smem + KS_OFF;
    float* Vs = smem + VS_OFF;
    float* Ps = smem + PS_OFF;

    const int tid = threadIdx.x;
    const int tx = tid & 15;   // key-col group (4 keys / 4 d-cols)
    const int ty = tid >> 4;   // query-row group (8 queries)
    const int bh = blockIdx.y;
    const int q0 = blockIdx.x * TQ;

    const float* Qg = Q + ((size_t)bh * SEQ + q0) * HDIM;
    const float* Kg = K + (size_t)bh * SEQ * HDIM;
    const float* Vg = V + (size_t)bh * SEQ * HDIM;

    // fold 1/sqrt(64) and log2(e) into Q so softmax uses ex2 directly
    const float qscale = 0.125f * 1.4426950408889634f;

    // ---- load Q tile transposed: Qs[d][q] ----
    {
        const int r = tid & 63;        // query row
        const int ch = tid >> 6;       // column half
#pragma unroll
        for (int it = 0; it < 8; it++) {
            int c4 = 2 * it + ch;      // d-group (4 d's)
            float4 v = *reinterpret_cast<const float4*>(Qg + r * HDIM + 4 * c4);
            Qs[(4 * c4 + 0) * QS_STRIDE + r] = v.x * qscale;
            Qs[(4 * c4 + 1) * QS_STRIDE + r] = v.y * qscale;
            Qs[(4 * c4 + 2) * QS_STRIDE + r] = v.z * qscale;
            Qs[(4 * c4 + 3) * QS_STRIDE + r] = v.w * qscale;
        }
    }

    ull o2[4][4];
#pragma unroll
    for (int i = 0; i < 4; i++)
#pragma unroll
        for (int j = 0; j < 4; j++) o2[i][j] = 0ULL;  // bits 0 == 0.0f pair

    float m[8], l[8];
#pragma unroll
    for (int q = 0; q < 8; q++) { m[q] = -INFINITY; l[q] = 0.0f; }

    for (int kt = 0; kt < SEQ; kt += TK) {
        __syncthreads();
        // ---- load K tile transposed Ks[d][k], V tile natural Vs[k][d] ----
        {
            const int r = tid & 63;
            const int ch = tid >> 6;
#pragma unroll
            for (int it = 0; it < 8; it++) {
                int c4 = 2 * it + ch;
                float4 v = *reinterpret_cast<const float4*>(Kg + (size_t)(kt + r) * HDIM + 4 * c4);
                Ks[(4 * c4 + 0) * KS_STRIDE + r] = v.x;
                Ks[(4 * c4 + 1) * KS_STRIDE + r] = v.y;
                Ks[(4 * c4 + 2) * KS_STRIDE + r] = v.z;
                Ks[(4 * c4 + 3) * KS_STRIDE + r] = v.w;
            }
            const float4* Vsrc = reinterpret_cast<const float4*>(Vg + (size_t)kt * HDIM);
            float4* Vdst = reinterpret_cast<float4*>(Vs);
#pragma unroll
            for (int it = 0; it < 8; it++) {
                int idx = it * NTHREADS + tid;
                Vdst[idx] = Vsrc[idx];
            }
        }
        __syncthreads();

        // ---- S = Q K^T (register tiled, f32x2 over query pairs) ----
        ull s2[4][4];
#pragma unroll
        for (int i = 0; i < 4; i++)
#pragma unroll
            for (int j = 0; j < 4; j++) s2[i][j] = 0ULL;

#pragma unroll 4
        for (int d = 0; d < HDIM; d++) {
            float4 qa = *reinterpret_cast<const float4*>(&Qs[d * QS_STRIDE + 8 * ty]);
            float4 qb = *reinterpret_cast<const float4*>(&Qs[d * QS_STRIDE + 8 * ty + 4]);
            float4 kf = *reinterpret_cast<const float4*>(&Ks[d * KS_STRIDE + 4 * tx]);
            ull qp[4];
            qp[0] = pack2(qa.x, qa.y);
            qp[1] = pack2(qa.z, qa.w);
            qp[2] = pack2(qb.x, qb.y);
            qp[3] = pack2(qb.z, qb.w);
            ull kp[4];
            kp[0] = pack2(kf.x, kf.x);
            kp[1] = pack2(kf.y, kf.y);
            kp[2] = pack2(kf.z, kf.z);
            kp[3] = pack2(kf.w, kf.w);
#pragma unroll
            for (int i = 0; i < 4; i++)
#pragma unroll
                for (int j = 0; j < 4; j++) fma2(s2[i][j], qp[i], kp[j]);
        }

        // ---- online softmax over this 64-key tile ----
        float mt[8];
#pragma unroll
        for (int i = 0; i < 4; i++) {
            float a, b;
            unpack2(s2[i][0], a, b);
            mt[2 * i] = a; mt[2 * i + 1] = b;
#pragma unroll
            for (int j = 1; j < 4; j++) {
                unpack2(s2[i][j], a, b);
                mt[2 * i] = fmaxf(mt[2 * i], a);
                mt[2 * i + 1] = fmaxf(mt[2 * i + 1], b);
            }
        }
#pragma unroll
        for (int q = 0; q < 8; q++) {
#pragma unroll
            for (int msk = 1; msk < 16; msk <<= 1)
                mt[q] = fmaxf(mt[q], __shfl_xor_sync(0xffffffffu, mt[q], msk));
        }
        float corr[8];
#pragma unroll
        for (int q = 0; q < 8; q++) {
            float mn = fmaxf(m[q], mt[q]);
            corr[q] = ex2(m[q] - mn);
            m[q] = mn;
            l[q] *= corr[q];
        }
#pragma unroll
        for (int i = 0; i < 4; i++) {
            ull c2 = pack2(corr[2 * i], corr[2 * i + 1]);
#pragma unroll
            for (int j = 0; j < 4; j++) mul2(o2[i][j], c2);
        }
        // p = ex2(s - m), accumulate l, store P transposed-ish: Ps[k][q]
#pragma unroll
        for (int i = 0; i < 4; i++) {
#pragma unroll
            for (int j = 0; j < 4; j++) {
                float a, b;
                unpack2(s2[i][j], a, b);
                float pa = ex2(a - m[2 * i]);
                float pb = ex2(b - m[2 * i + 1]);
                l[2 * i] += pa;
                l[2 * i + 1] += pb;
                *reinterpret_cast<ull*>(&Ps[(4 * tx + j) * PS_STRIDE + 8 * ty + 2 * i]) = pack2(pa, pb);
            }
        }
        __syncthreads();

        // ---- O += P V (register tiled, same query pairing) ----
#pragma unroll 4
        for (int k = 0; k < TK; k++) {
            const float* pr = &Ps[k * PS_STRIDE + 8 * ty];
            ull p2[4];
#pragma unroll
            for (int i = 0; i < 4; i++)
                p2[i] = *reinterpret_cast<const ull*>(pr + 2 * i);
            float4 vf = *reinterpret_cast<const float4*>(&Vs[k * VS_STRIDE + 4 * tx]);
            ull vp[4];
            vp[0] = pack2(vf.x, vf.x);
            vp[1] = pack2(vf.y, vf.y);
            vp[2] = pack2(vf.z, vf.z);
            vp[3] = pack2(vf.w, vf.w);
#pragma unroll
            for (int i = 0; i < 4; i++)
#pragma unroll
                for (int j = 0; j < 4; j++) fma2(o2[i][j], p2[i], vp[j]);
        }
    }

    // ---- final: reduce l across the 16 key-lanes, normalize, write ----
#pragma unroll
    for (int q = 0; q < 8; q++) {
#pragma unroll
        for (int msk = 1; msk < 16; msk <<= 1)
            l[q] += __shfl_xor_sync(0xffffffffu, l[q], msk);
    }
    float* Og = O + ((size_t)bh * SEQ + q0) * HDIM;
#pragma unroll
    for (int i = 0; i < 4; i++) {
        float inva = 1.0f / l[2 * i];
        float invb = 1.0f / l[2 * i + 1];
#pragma unroll
        for (int j = 0; j < 4; j++) {
            float a, b;
            unpack2(o2[i][j], a, b);
            Og[(size_t)(8 * ty + 2 * i) * HDIM + 4 * tx + j] = a * inva;
            Og[(size_t)(8 * ty + 2 * i + 1) * HDIM + 4 * tx + j] = b * invb;
        }
    }
}

extern "C" void kernel_launch(void* const* d_in, const int* in_sizes, int n_in,
                              void* d_out, int out_size) {
    const float* Q = (const float*)d_in[0];
    const float* K = (const float*)d_in[1];
    const float* V = (const float*)d_in[2];
    float* O = (float*)d_out;

    cudaFuncSetAttribute(sdpa_rt_kernel, cudaFuncAttributeMaxDynamicSharedMemorySize, SMEM_BYTES);

    dim3 grid(SEQ / TQ, BATCH * HEADS);
    dim3 block(NTHREADS);
    sdpa_rt_kernel<<<grid, block, SMEM_BYTES>>>(Q, K, V, O);
}

// round 15
// speedup vs baseline: 1.6949x; 1.1135x over previous
#include <cuda_runtime.h>
#include <math.h>
#include <stdint.h>

// SDPA B=4,H=16,S=2048,D=64 fp32 — flash attention on tensor cores.
// mma.sync m16n8k8 tf32 with 3xTF32 split for fp32-grade accuracy.
// CTA: 64 queries x 64 keys per tile, 4 warps (16 q each).

#define BATCH 4
#define HEADS 16
#define SEQ   2048
#define HDIM  64
#define TQ    64
#define TK    64
#define NTHREADS 128

// smem strides (floats), chosen so every fragment access is bank-conflict-free:
// K natural [key][d], B-frag addr = key*68 + d  -> (4k+d) mod 32 all distinct
// V natural [key][d], B-frag addr = key*72 + d  -> (8k+d) mod 32 all distinct
// P [q][k],           A-frag addr = q*68 + k    -> (4g+t) mod 32 all distinct
#define KSD 68
#define VSD 72
#define PSD 68
#define KOFF 0
#define VOFF (64 * KSD)
#define POFF (VOFF + 64 * VSD)
#define SMEM_FLOATS (POFF + 64 * PSD)
#define SMEM_BYTES (SMEM_FLOATS * 4)

__device__ __forceinline__ uint32_t f2tf(float f) {
    uint32_t r;
    asm("cvt.rna.tf32.f32 %0, %1;" : "=r"(r) : "f"(f));
    return r;
}
// 3xTF32 split: hi = tf32(f) (exact in fp32), lo = tf32(f - hi)
__device__ __forceinline__ void tfsplit(float f, uint32_t& hi, uint32_t& lo) {
    hi = f2tf(f);
    lo = f2tf(f - __uint_as_float(hi));
}
__device__ __forceinline__ void mma_tf32(float4& d, const uint32_t a[4],
                                         uint32_t b0, uint32_t b1) {
    asm volatile(
        "mma.sync.aligned.m16n8k8.row.col.f32.tf32.tf32.f32 "
        "{%0,%1,%2,%3}, {%4,%5,%6,%7}, {%8,%9}, {%0,%1,%2,%3};"
        : "+f"(d.x), "+f"(d.y), "+f"(d.z), "+f"(d.w)
        : "r"(a[0]), "r"(a[1]), "r"(a[2]), "r"(a[3]), "r"(b0), "r"(b1));
}
__device__ __forceinline__ float ex2f(float x) {
    float y;
    asm("ex2.approx.ftz.f32 %0, %1;" : "=f"(y) : "f"(x));
    return y;
}

extern __shared__ float smem[];

__global__ void __launch_bounds__(NTHREADS)
sdpa_mma_kernel(const float* __restrict__ Q,
                const float* __restrict__ K,
                const float* __restrict__ V,
                float* __restrict__ O) {
    float* Ks = smem + KOFF;
    float* Vs = smem + VOFF;
    float* Ps = smem + POFF;

    const int tid  = threadIdx.x;
    const int lane = tid & 31;
    const int warp = tid >> 5;
    const int g    = lane >> 2;   // fragment group row
    const int tig  = lane & 3;    // thread-in-group
    const int bh   = blockIdx.y;
    const int q0   = blockIdx.x * TQ;

    const float* Qg = Q + ((size_t)bh * SEQ + q0) * HDIM;
    const float* Kg = K + (size_t)bh * SEQ * HDIM;
    const float* Vg = V + (size_t)bh * SEQ * HDIM;

    // fold 1/sqrt(64) and log2(e) into Q so softmax uses ex2 directly
    const float qscale = 0.125f * 1.4426950408889634f;

    // ---- stage Q (prescaled) into Ps buffer, then pull A-fragments ----
    for (int i = 0; i < 8; i++) {
        int idx = i * NTHREADS + tid;
        int r = idx >> 4, c4 = idx & 15;
        float4 v = *reinterpret_cast<const float4*>(Qg + r * HDIM + 4 * c4);
        v.x *= qscale; v.y *= qscale; v.z *= qscale; v.w *= qscale;
        *reinterpret_cast<float4*>(&Ps[r * PSD + 4 * c4]) = v;
    }
    __syncthreads();

    // Q fragments for all 8 k-steps, hi/lo split (held in registers all kernel)
    uint32_t qhi[8][4], qlo[8][4];
    {
        const int rb = 16 * warp + g;
#pragma unroll
        for (int k = 0; k < 8; k++) {
            float f0 = Ps[rb * PSD + 8 * k + tig];            // (g,     t)
            float f1 = Ps[(rb + 8) * PSD + 8 * k + tig];      // (g+8,   t)
            float f2 = Ps[rb * PSD + 8 * k + tig + 4];        // (g,   t+4)
            float f3 = Ps[(rb + 8) * PSD + 8 * k + tig + 4];  // (g+8, t+4)
            tfsplit(f0, qhi[k][0], qlo[k][0]);
            tfsplit(f1, qhi[k][1], qlo[k][1]);
            tfsplit(f2, qhi[k][2], qlo[k][2]);
            tfsplit(f3, qhi[k][3], qlo[k][3]);
        }
    }

    float4 o[8];
#pragma unroll
    for (int n = 0; n < 8; n++) o[n] = make_float4(0.f, 0.f, 0.f, 0.f);
    float m0 = -INFINITY, m1 = -INFINITY, l0 = 0.f, l1 = 0.f;

    for (int kt = 0; kt < SEQ; kt += TK) {
        __syncthreads();   // previous tile's K/V reads complete before overwrite
        // ---- load K,V tiles natural [key][d] with padded strides ----
        for (int i = 0; i < 8; i++) {
            int idx = i * NTHREADS + tid;
            int r = idx >> 4, c4 = idx & 15;
            *reinterpret_cast<float4*>(&Ks[r * KSD + 4 * c4]) =
                *reinterpret_cast<const float4*>(Kg + (size_t)(kt + r) * HDIM + 4 * c4);
            *reinterpret_cast<float4*>(&Vs[r * VSD + 4 * c4]) =
                *reinterpret_cast<const float4*>(Vg + (size_t)(kt + r) * HDIM + 4 * c4);
        }
        __syncthreads();

        // ---- S = Q K^T, 3xTF32 ----
        float4 s[8];
#pragma unroll
        for (int n = 0; n < 8; n++) s[n] = make_float4(0.f, 0.f, 0.f, 0.f);

#pragma unroll
        for (int k = 0; k < 8; k++) {
#pragma unroll
            for (int n = 0; n < 8; n++) {
                // B-frag element (d=8k+tig(+4), key=8n+g) = K[key][d]
                int ba = (8 * n + g) * KSD + 8 * k + tig;
                uint32_t b0h, b0l, b1h, b1l;
                tfsplit(Ks[ba], b0h, b0l);
                tfsplit(Ks[ba + 4], b1h, b1l);
                mma_tf32(s[n], qhi[k], b0h, b1h);
                mma_tf32(s[n], qlo[k], b0h, b1h);
                mma_tf32(s[n], qhi[k], b0l, b1l);
            }
        }

        // ---- online softmax (C-layout: rows g and g+8, cols 2*tig+{0,1}+8n) ----
        float mx0 = s[0].x, mx1 = s[0].z;
#pragma unroll
        for (int n = 0; n < 8; n++) {
            mx0 = fmaxf(mx0, fmaxf(s[n].x, s[n].y));
            mx1 = fmaxf(mx1, fmaxf(s[n].z, s[n].w));
        }
        mx0 = fmaxf(mx0, __shfl_xor_sync(0xffffffffu, mx0, 1));
        mx0 = fmaxf(mx0, __shfl_xor_sync(0xffffffffu, mx0, 2));
        mx1 = fmaxf(mx1, __shfl_xor_sync(0xffffffffu, mx1, 1));
        mx1 = fmaxf(mx1, __shfl_xor_sync(0xffffffffu, mx1, 2));

        float mn0 = fmaxf(m0, mx0), mn1 = fmaxf(m1, mx1);
        float c0 = ex2f(m0 - mn0), c1 = ex2f(m1 - mn1);
        m0 = mn0; m1 = mn1;
        l0 *= c0; l1 *= c1;
#pragma unroll
        for (int n = 0; n < 8; n++) {
            o[n].x *= c0; o[n].y *= c0;
            o[n].z *= c1; o[n].w *= c1;
        }

        const int prow = (16 * warp + g) * PSD;
#pragma unroll
        for (int n = 0; n < 8; n++) {
            float px = ex2f(s[n].x - m0), py = ex2f(s[n].y - m0);
            float pz = ex2f(s[n].z - m1), pw = ex2f(s[n].w - m1);
            l0 += px + py;
            l1 += pz + pw;
            *reinterpret_cast<float2*>(&Ps[prow + 8 * n + 2 * tig]) = make_float2(px, py);
            *reinterpret_cast<float2*>(&Ps[prow + 8 * PSD + 8 * n + 2 * tig]) = make_float2(pz, pw);
        }
        __syncwarp();   // P rows are warp-private; STS->LDS visibility

        // ---- O += P V, 3xTF32 ----
#pragma unroll
        for (int k = 0; k < 8; k++) {
            uint32_t phi[4], plo[4];
            int ab = (16 * warp + g) * PSD + 8 * k + tig;
            tfsplit(Ps[ab], phi[0], plo[0]);               // (g,     key t)
            tfsplit(Ps[ab + 8 * PSD], phi[1], plo[1]);     // (g+8,   t)
            tfsplit(Ps[ab + 4], phi[2], plo[2]);           // (g,   t+4)
            tfsplit(Ps[ab + 8 * PSD + 4], phi[3], plo[3]); // (g+8, t+4)
#pragma unroll
            for (int n = 0; n < 8; n++) {
                // B-frag element (key=8k+tig(+4), d=8n+g) = V[key][d]
                int vb = (8 * k + tig) * VSD + 8 * n + g;
                uint32_t b0h, b0l, b1h, b1l;
                tfsplit(Vs[vb], b0h, b0l);
                tfsplit(Vs[vb + 4 * VSD], b1h, b1l);
                mma_tf32(o[n], phi, b0h, b1h);
                mma_tf32(o[n], plo, b0h, b1h);
                mma_tf32(o[n], phi, b0l, b1l);
            }
        }
        __syncwarp();   // PV reads of Ps complete before next tile's P store
    }

    // ---- final: reduce l across the 4 lanes of each row group, write O ----
    l0 += __shfl_xor_sync(0xffffffffu, l0, 1);
    l0 += __shfl_xor_sync(0xffffffffu, l0, 2);
    l1 += __shfl_xor_sync(0xffffffffu, l1, 1);
    l1 += __shfl_xor_sync(0xffffffffu, l1, 2);
    const float i0 = 1.0f / l0, i1 = 1.0f / l1;

    float* Og = O + ((size_t)bh * SEQ + q0) * HDIM;
    const int r0 = 16 * warp + g, r1 = r0 + 8;
#pragma unroll
    for (int n = 0; n < 8; n++) {
        int cc = 8 * n + 2 * tig;
        *reinterpret_cast<float2*>(&Og[(size_t)r0 * HDIM + cc]) =
            make_float2(o[n].x * i0, o[n].y * i0);
        *reinterpret_cast<float2*>(&Og[(size_t)r1 * HDIM + cc]) =
            make_float2(o[n].z * i1, o[n].w * i1);
    }
}

extern "C" void kernel_launch(void* const* d_in, const int* in_sizes, int n_in,
                              void* d_out, int out_size) {
    const float* Q = (const float*)d_in[0];
    const float* K = (const float*)d_in[1];
    const float* V = (const float*)d_in[2];
    float* O = (float*)d_out;

    cudaFuncSetAttribute(sdpa_mma_kernel, cudaFuncAttributeMaxDynamicSharedMemorySize, SMEM_BYTES);

    dim3 grid(SEQ / TQ, BATCH * HEADS);
    dim3 block(NTHREADS);
    sdpa_mma_kernel<<<grid, block, SMEM_BYTES>>>(Q, K, V, O);
}